// round 1
// baseline (speedup 1.0000x reference)
#include <cuda_runtime.h>
#include <cuda_bf16.h>

// Problem shape (fixed by the dataset)
#define NROWS 16384
#define MCOLS 4096
#define DDIM  512

#define BN 128
#define BM 128
#define BK 16

// Scratch (no device allocations allowed -> __device__ globals)
__device__ float g_xsq[NROWS];
__device__ float g_ssq[MCOLS];
__device__ float g_dec[NROWS];

// ---------------------------------------------------------------------------
// Kernel A: row squared-norms for X and S, and zero the decision accumulator.
// One warp per row; lanes stride the 128 float4s of a 512-float row.
// ---------------------------------------------------------------------------
__global__ void precompute_kernel(const float* __restrict__ X,
                                  const float* __restrict__ S) {
    int gwarp = (blockIdx.x * blockDim.x + threadIdx.x) >> 5;
    int lane  = threadIdx.x & 31;

    if (gwarp < NROWS) {
        const float4* p = (const float4*)(X + (size_t)gwarp * DDIM);
        float s = 0.f;
        #pragma unroll 4
        for (int i = lane; i < DDIM / 4; i += 32) {
            float4 v = p[i];
            s += v.x * v.x + v.y * v.y + v.z * v.z + v.w * v.w;
        }
        #pragma unroll
        for (int off = 16; off; off >>= 1)
            s += __shfl_down_sync(0xffffffffu, s, off);
        if (lane == 0) {
            g_xsq[gwarp] = s;
            g_dec[gwarp] = 0.f;
        }
    } else if (gwarp < NROWS + MCOLS) {
        int row = gwarp - NROWS;
        const float4* p = (const float4*)(S + (size_t)row * DDIM);
        float s = 0.f;
        #pragma unroll 4
        for (int i = lane; i < DDIM / 4; i += 32) {
            float4 v = p[i];
            s += v.x * v.x + v.y * v.y + v.z * v.z + v.w * v.w;
        }
        #pragma unroll
        for (int off = 16; off; off >>= 1)
            s += __shfl_down_sync(0xffffffffu, s, off);
        if (lane == 0) g_ssq[row] = s;
    }
}

// ---------------------------------------------------------------------------
// Kernel B: tiled GEMM (cross = X @ S^T) with fused RBF epilogue.
// Block tile 128x128, K-step 16, 256 threads, per-thread 8x8 microtile.
// Epilogue: dist = xsq + ssq - 2*cross; e = exp(-dist/(2 sigma^2));
//           partial[n] += e * alpha[m]; reduce over the 16 tx-threads of the
//           same row group; atomicAdd into g_dec.
// ---------------------------------------------------------------------------
__global__ __launch_bounds__(256)
void svm_main_kernel(const float* __restrict__ X,
                     const float* __restrict__ S,
                     const float* __restrict__ alphas,
                     const float* __restrict__ sigma) {
    __shared__ float As[BK][BN];
    __shared__ float Bs[BK][BM];

    const int bn = blockIdx.y * BN;
    const int bm = blockIdx.x * BM;
    const int tid = threadIdx.x;         // 0..255
    const int tx = tid & 15;             // 0..15  -> column group (8 cols)
    const int ty = tid >> 4;             // 0..15  -> row group    (8 rows)

    float acc[8][8];
    #pragma unroll
    for (int i = 0; i < 8; i++)
        #pragma unroll
        for (int j = 0; j < 8; j++) acc[i][j] = 0.f;

    for (int k0 = 0; k0 < DDIM; k0 += BK) {
        // Load X tile: 128 rows x 16 cols = 512 float4, 2 per thread.
        #pragma unroll
        for (int r = 0; r < 2; r++) {
            int idx = tid + r * 256;          // 0..511
            int row = idx >> 2;               // 4 float4 per row
            int c4  = idx & 3;
            float4 v = *(const float4*)(X + (size_t)(bn + row) * DDIM + k0 + c4 * 4);
            As[c4 * 4 + 0][row] = v.x;
            As[c4 * 4 + 1][row] = v.y;
            As[c4 * 4 + 2][row] = v.z;
            As[c4 * 4 + 3][row] = v.w;
        }
        // Load S tile (S is [M, D] row-major; we need S^T columns = S rows).
        #pragma unroll
        for (int r = 0; r < 2; r++) {
            int idx = tid + r * 256;
            int row = idx >> 2;
            int c4  = idx & 3;
            float4 v = *(const float4*)(S + (size_t)(bm + row) * DDIM + k0 + c4 * 4);
            Bs[c4 * 4 + 0][row] = v.x;
            Bs[c4 * 4 + 1][row] = v.y;
            Bs[c4 * 4 + 2][row] = v.z;
            Bs[c4 * 4 + 3][row] = v.w;
        }
        __syncthreads();

        #pragma unroll
        for (int k = 0; k < BK; k++) {
            float a[8], b[8];
            #pragma unroll
            for (int i = 0; i < 8; i++) a[i] = As[k][ty * 8 + i];
            #pragma unroll
            for (int j = 0; j < 8; j++) b[j] = Bs[k][tx * 8 + j];
            #pragma unroll
            for (int i = 0; i < 8; i++)
                #pragma unroll
                for (int j = 0; j < 8; j++)
                    acc[i][j] += a[i] * b[j];
        }
        __syncthreads();
    }

    // ---------------- Epilogue ----------------
    const float sg = *sigma;
    const float inv2s2 = 1.0f / (2.0f * sg * sg);

    float bvals_ssq[8], bvals_al[8];
    #pragma unroll
    for (int j = 0; j < 8; j++) {
        int col = bm + tx * 8 + j;
        bvals_ssq[j] = g_ssq[col];
        bvals_al[j]  = alphas[col];
    }

    #pragma unroll
    for (int i = 0; i < 8; i++) {
        int row = bn + ty * 8 + i;
        float xs = g_xsq[row];
        float p = 0.f;
        #pragma unroll
        for (int j = 0; j < 8; j++) {
            float dist = xs + bvals_ssq[j] - 2.0f * acc[i][j];
            float arg = -dist * inv2s2;
            // flush-to-zero fast path: exp(arg) == 0 in fp32 for arg < ~ -87.3
            float e = (arg > -87.0f) ? __expf(arg) : 0.0f;
            p += e * bvals_al[j];
        }
        // Reduce across the 16 threads (same ty, tx = 0..15) that share row.
        // tid = ty*16+tx, so they are 16 consecutive lanes -> width-16 shuffle.
        #pragma unroll
        for (int off = 8; off; off >>= 1)
            p += __shfl_down_sync(0xffffffffu, p, off, 16);
        if (tx == 0) atomicAdd(&g_dec[row], p);
    }
}

// ---------------------------------------------------------------------------
// Kernel C: out[n] = sign(decision[n] + bias)
// ---------------------------------------------------------------------------
__global__ void sign_kernel(const float* __restrict__ bias, float* __restrict__ out) {
    int n = blockIdx.x * blockDim.x + threadIdx.x;
    if (n < NROWS) {
        float d = g_dec[n] + bias[0];
        out[n] = (d > 0.f) ? 1.0f : ((d < 0.f) ? -1.0f : 0.0f);
    }
}

// ---------------------------------------------------------------------------
extern "C" void kernel_launch(void* const* d_in, const int* in_sizes, int n_in,
                              void* d_out, int out_size) {
    const float* X      = (const float*)d_in[0];   // [16384, 512]
    const float* S      = (const float*)d_in[1];   // [4096, 512]
    const float* alphas = (const float*)d_in[2];   // [4096]
    const float* bias   = (const float*)d_in[3];   // [1]
    const float* sigma  = (const float*)d_in[4];   // scalar
    float* out          = (float*)d_out;           // [16384]

    // A: norms + zero accumulator. (NROWS + MCOLS) warps, 8 warps/block.
    {
        int warps = NROWS + MCOLS;
        int blocks = (warps * 32 + 255) / 256;
        precompute_kernel<<<blocks, 256>>>(X, S);
    }
    // B: fused GEMM + RBF epilogue.
    {
        dim3 grid(MCOLS / BM, NROWS / BN);  // (32, 128)
        svm_main_kernel<<<grid, 256>>>(X, S, alphas, sigma);
    }
    // C: sign.
    {
        sign_kernel<<<(NROWS + 255) / 256, 256>>>(bias, out);
    }
}

// round 4
// speedup vs baseline: 8.5178x; 8.5178x over previous
#include <cuda_runtime.h>
#include <cuda_bf16.h>
#include <cstdint>

// Problem shape (fixed by the dataset)
#define NROWS 16384
#define MCOLS 4096
#define DDIM  512

#define BM 128          // X rows per CTA
#define BN 128          // S rows (output cols) per CTA
#define BK 64           // bf16 K elements per chunk (= 128 bytes per row)
#define NCHUNKS (DDIM / BK)   // 8

// ---------------- scratch (device globals; no runtime allocs) ---------------
__device__ float g_xsq[NROWS];
__device__ float g_ssq[MCOLS];
__device__ float g_dec[NROWS];
__device__ __nv_bfloat16 g_Xb[(size_t)NROWS * DDIM];  // 16 MB
__device__ __nv_bfloat16 g_Sb[(size_t)MCOLS * DDIM];  //  4 MB

// ---------------- SMEM layout ------------------------------------------------
// A: 128 rows x 128 B = 16 KB per buffer, B same. Double buffered: 64 KB.
// + 1 KB epilogue (ssq/alpha caches).
#define SMA(buf)  ((buf) * 16384)                 // A buffers at 0, 16K
#define SMB(buf)  (32768 + (buf) * 16384)         // B buffers at 32K, 48K
#define SM_EPI    65536
#define SM_TOTAL  (65536 + 1024)

__device__ __forceinline__ uint32_t smem_u32(const void* p) {
    uint32_t a;
    asm("{ .reg .u64 t; cvta.to.shared.u64 t, %1; cvt.u32.u64 %0, t; }" : "=r"(a) : "l"(p));
    return a;
}
__device__ __forceinline__ uint32_t sw128(uint32_t off) { return off ^ ((off >> 3) & 0x70); }

#define CP_ASYNC_16(dst, src) \
    asm volatile("cp.async.cg.shared.global [%0], [%1], 16;" :: "r"(dst), "l"(src) : "memory")
#define CP_ASYNC_COMMIT() asm volatile("cp.async.commit_group;" ::: "memory")
#define CP_ASYNC_WAIT(n)  asm volatile("cp.async.wait_group %0;" :: "n"(n) : "memory")

#define LDSM_X4(r0, r1, r2, r3, addr) \
    asm volatile("ldmatrix.sync.aligned.m8n8.x4.shared.b16 {%0,%1,%2,%3}, [%4];" \
                 : "=r"(r0), "=r"(r1), "=r"(r2), "=r"(r3) : "r"(addr))

#define MMA_BF16(c0, c1, c2, c3, a0, a1, a2, a3, b0, b1)                      \
    asm volatile("mma.sync.aligned.m16n8k16.row.col.f32.bf16.bf16.f32 "       \
                 "{%0,%1,%2,%3}, {%4,%5,%6,%7}, {%8,%9}, {%0,%1,%2,%3};"      \
                 : "+f"(c0), "+f"(c1), "+f"(c2), "+f"(c3)                     \
                 : "r"(a0), "r"(a1), "r"(a2), "r"(a3), "r"(b0), "r"(b1))

// ---------------------------------------------------------------------------
// Kernel A: bf16 convert + row squared-norms + zero decision accumulator.
// One warp per row.
// ---------------------------------------------------------------------------
__global__ void prep_kernel(const float* __restrict__ X, const float* __restrict__ S) {
    int gwarp = (blockIdx.x * blockDim.x + threadIdx.x) >> 5;
    int lane  = threadIdx.x & 31;

    const float* src;
    __nv_bfloat16* dst;
    int row;
    bool isX;
    if (gwarp < NROWS) {
        row = gwarp; src = X; dst = g_Xb; isX = true;
    } else if (gwarp < NROWS + MCOLS) {
        row = gwarp - NROWS; src = S; dst = g_Sb; isX = false;
    } else return;

    const float4* p = (const float4*)(src + (size_t)row * DDIM);
    __nv_bfloat162* q = (__nv_bfloat162*)(dst + (size_t)row * DDIM);
    float s = 0.f;
    #pragma unroll
    for (int t = 0; t < DDIM / 4 / 32; t++) {
        int i = lane + t * 32;
        float4 v = p[i];
        s += v.x * v.x + v.y * v.y + v.z * v.z + v.w * v.w;
        q[2 * i + 0] = __float22bfloat162_rn(make_float2(v.x, v.y));
        q[2 * i + 1] = __float22bfloat162_rn(make_float2(v.z, v.w));
    }
    #pragma unroll
    for (int off = 16; off; off >>= 1) s += __shfl_down_sync(0xffffffffu, s, off);
    if (lane == 0) {
        if (isX) { g_xsq[row] = s; g_dec[row] = 0.f; }
        else     { g_ssq[row] = s; }
    }
}

// ---------------------------------------------------------------------------
// Kernel B: bf16 mma.sync GEMM (cross = X @ S^T) with fused RBF epilogue.
// 128x128 CTA tile, BK=64, cp.async double buffering, 8 warps (4x2),
// warp tile 32x64, mma m16n8k16.
// ---------------------------------------------------------------------------
__global__ __launch_bounds__(256)
void svm_mma_kernel(const float* __restrict__ alphas,
                    const float* __restrict__ sigma) {
    extern __shared__ char smem[];
    const uint32_t smem_base = smem_u32(smem);
    const int tid  = threadIdx.x;
    const int wid  = tid >> 5;
    const int lane = tid & 31;

    const int bn = blockIdx.y * BM;       // X rows
    const int bm = blockIdx.x * BN;       // S rows (output columns)

    const int warpM = (wid & 3) * 32;     // warp row offset in tile
    const int warpN = (wid >> 2) * 64;    // warp col offset in tile

    // Per-thread cp.async source/dest fragments (4 x 16B for A, 4 for B)
    // idx = tid + t*256 in [0,1024): row = idx>>3, 16B-col = idx&7.
    const __nv_bfloat16* Xb = g_Xb;
    const __nv_bfloat16* Sb = g_Sb;

    float acc[2][8][4];
    #pragma unroll
    for (int mi = 0; mi < 2; mi++)
        #pragma unroll
        for (int ni = 0; ni < 8; ni++)
            #pragma unroll
            for (int k = 0; k < 4; k++) acc[mi][ni][k] = 0.f;

    // ldmatrix lane addressing (byte offsets inside a buffer, pre-swizzle):
    // A x4 tile (16x16): row = (l&7) + ((l>>3)&1)*8, ksel = (l>>4)&1
    const int aRow  = (lane & 7) + ((lane >> 3) & 1) * 8;
    const int aKoff = ((lane >> 4) & 1) * 16;
    // B x4 covers 16 n-rows x 16 k: row = (l&7) + ((l>>4)&1)*8, ksel = (l>>3)&1
    const int bRow  = (lane & 7) + ((lane >> 4) & 1) * 8;
    const int bKoff = ((lane >> 3) & 1) * 16;

    auto load_chunk = [&](int c, int buf) {
        const int k0 = c * BK;
        #pragma unroll
        for (int t = 0; t < 4; t++) {
            int idx = tid + t * 256;
            int row = idx >> 3;
            int c16 = idx & 7;
            uint32_t d = smem_base + SMA(buf) + sw128(row * 128 + c16 * 16);
            CP_ASYNC_16(d, Xb + (size_t)(bn + row) * DDIM + k0 + c16 * 8);
        }
        #pragma unroll
        for (int t = 0; t < 4; t++) {
            int idx = tid + t * 256;
            int row = idx >> 3;
            int c16 = idx & 7;
            uint32_t d = smem_base + SMB(buf) + sw128(row * 128 + c16 * 16);
            CP_ASYNC_16(d, Sb + (size_t)(bm + row) * DDIM + k0 + c16 * 8);
        }
        CP_ASYNC_COMMIT();
    };

    load_chunk(0, 0);

    for (int c = 0; c < NCHUNKS; c++) {
        const int buf = c & 1;
        if (c + 1 < NCHUNKS) {
            load_chunk(c + 1, buf ^ 1);
            CP_ASYNC_WAIT(1);
        } else {
            CP_ASYNC_WAIT(0);
        }
        __syncthreads();

        const uint32_t sa = smem_base + SMA(buf);
        const uint32_t sb = smem_base + SMB(buf);

        #pragma unroll
        for (int ks = 0; ks < 4; ks++) {
            // A fragments for the two 16-row m-tiles
            uint32_t a[2][4];
            #pragma unroll
            for (int mi = 0; mi < 2; mi++) {
                uint32_t addr = sa + sw128((warpM + mi * 16 + aRow) * 128 + ks * 32 + aKoff);
                LDSM_X4(a[mi][0], a[mi][1], a[mi][2], a[mi][3], addr);
            }
            // B fragments: 4 x4-loads cover 8 n-tiles (16 n each)
            uint32_t b[8][2];
            #pragma unroll
            for (int nj = 0; nj < 4; nj++) {
                uint32_t addr = sb + sw128((warpN + nj * 16 + bRow) * 128 + ks * 32 + bKoff);
                uint32_t r0, r1, r2, r3;
                LDSM_X4(r0, r1, r2, r3, addr);
                b[nj * 2 + 0][0] = r0; b[nj * 2 + 0][1] = r1;
                b[nj * 2 + 1][0] = r2; b[nj * 2 + 1][1] = r3;
            }
            #pragma unroll
            for (int mi = 0; mi < 2; mi++)
                #pragma unroll
                for (int ni = 0; ni < 8; ni++)
                    MMA_BF16(acc[mi][ni][0], acc[mi][ni][1], acc[mi][ni][2], acc[mi][ni][3],
                             a[mi][0], a[mi][1], a[mi][2], a[mi][3],
                             b[ni][0], b[ni][1]);
        }
        __syncthreads();
    }

    // ---------------- Epilogue ----------------
    float* sh_ssq = (float*)(smem + SM_EPI);        // 128 floats
    float* sh_al  = sh_ssq + 128;                   // 128 floats
    if (tid < 128) {
        sh_ssq[tid] = g_ssq[bm + tid];
        sh_al[tid]  = alphas[bm + tid];
    }
    __syncthreads();

    const float sg = *sigma;
    const float inv2s2 = 1.0f / (2.0f * sg * sg);

    const int gq = lane >> 2;   // C fragment row group (0..7)
    const int q  = lane & 3;    // C fragment col group (0..3)

    #pragma unroll
    for (int mi = 0; mi < 2; mi++) {
        int r0 = warpM + mi * 16 + gq;      // local row of c0/c1
        int r1 = r0 + 8;                    // local row of c2/c3
        float xs0 = g_xsq[bn + r0];
        float xs1 = g_xsq[bn + r1];
        float p0 = 0.f, p1 = 0.f;
        #pragma unroll
        for (int ni = 0; ni < 8; ni++) {
            int j = warpN + ni * 8 + q * 2;
            float ss0 = sh_ssq[j],     al0 = sh_al[j];
            float ss1 = sh_ssq[j + 1], al1 = sh_al[j + 1];

            float arg;
            arg = -(xs0 + ss0 - 2.0f * acc[mi][ni][0]) * inv2s2;
            if (arg > -87.0f) p0 += __expf(arg) * al0;
            arg = -(xs0 + ss1 - 2.0f * acc[mi][ni][1]) * inv2s2;
            if (arg > -87.0f) p0 += __expf(arg) * al1;
            arg = -(xs1 + ss0 - 2.0f * acc[mi][ni][2]) * inv2s2;
            if (arg > -87.0f) p1 += __expf(arg) * al0;
            arg = -(xs1 + ss1 - 2.0f * acc[mi][ni][3]) * inv2s2;
            if (arg > -87.0f) p1 += __expf(arg) * al1;
        }
        // Reduce across the 4 lanes (same gq, q = 0..3) sharing each row.
        p0 += __shfl_down_sync(0xffffffffu, p0, 2, 4);
        p0 += __shfl_down_sync(0xffffffffu, p0, 1, 4);
        p1 += __shfl_down_sync(0xffffffffu, p1, 2, 4);
        p1 += __shfl_down_sync(0xffffffffu, p1, 1, 4);
        if (q == 0) {
            atomicAdd(&g_dec[bn + r0], p0);
            atomicAdd(&g_dec[bn + r1], p1);
        }
    }
}

// ---------------------------------------------------------------------------
// Kernel C: out[n] = sign(decision[n] + bias)
// ---------------------------------------------------------------------------
__global__ void sign_kernel(const float* __restrict__ bias, float* __restrict__ out) {
    int n = blockIdx.x * blockDim.x + threadIdx.x;
    if (n < NROWS) {
        float d = g_dec[n] + bias[0];
        out[n] = (d > 0.f) ? 1.0f : ((d < 0.f) ? -1.0f : 0.0f);
    }
}

// ---------------------------------------------------------------------------
extern "C" void kernel_launch(void* const* d_in, const int* in_sizes, int n_in,
                              void* d_out, int out_size) {
    const float* X      = (const float*)d_in[0];   // [16384, 512]
    const float* S      = (const float*)d_in[1];   // [4096, 512]
    const float* alphas = (const float*)d_in[2];   // [4096]
    const float* bias   = (const float*)d_in[3];   // [1]
    const float* sigma  = (const float*)d_in[4];   // scalar

    cudaFuncSetAttribute(svm_mma_kernel, cudaFuncAttributeMaxDynamicSharedMemorySize, SM_TOTAL);

    {   // A: convert + norms + zero accumulator
        int warps = NROWS + MCOLS;
        int blocks = (warps * 32 + 255) / 256;
        prep_kernel<<<blocks, 256>>>(X, S);
    }
    {   // B: mma.sync GEMM + fused RBF epilogue
        dim3 grid(MCOLS / BN, NROWS / BM);  // (32, 128)
        svm_mma_kernel<<<grid, 256, SM_TOTAL>>>(alphas, sigma);
    }
    {   // C: sign
        sign_kernel<<<(NROWS + 255) / 256, 256>>>(bias, (float*)d_out);
    }
}